// round 17
// baseline (speedup 1.0000x reference)
#include <cuda_runtime.h>
#include <cuda_fp16.h>
#include <cstdint>

#define NB 512   // buckets
#define ND 256   // feature dim
#define NMAX 100352
#define NCNT_BLK 56

#define SE_STRIDE 520          // halves per row of exp tile (512 + 8 pad)
#define SE_OFF 0               // 64 x 520 halves = 66560 B
#define SB_OFF 66560           // per-warp B double buffers: 8 x 2 x 2560 B
#define SB_WARP 5120           // 2 bufs x 2560
#define SB_BUF 2560            // 32 n-rows x 80 B
#define STG_OFF 107520         // logits staging: 2 x 32KB (16 rows x 2KB)
#define STG_BUF 32768
#define XCOEF_OFF 173056       // 64 floats
#define SMEM_TOTAL (173056 + 256 + 32)
#define SH_STRIDE 264          // fp32 epilogue tile stride (overlaps sE/sB region)

// ---------------- device scratch (no allocation allowed) ----------------
__device__ float g_sums[NB * ND];
__device__ float g_counts[NB];
__device__ int   g_pcnt[NCNT_BLK][NB];
__device__ int   g_off[NB + 1];
__device__ int   g_cursor[NB];
__device__ int   g_perm[NMAX];
__device__ int   g_tick1;
__device__ int   g_tick2;
__device__ __align__(16) __half g_P2t[ND * NB];  // (proto @ W_r^T)^T fp16, [d2][b]

// ---------------- helpers ----------------
__device__ __forceinline__ uint32_t smem_u32(const void* p) {
    uint32_t a;
    asm("{ .reg .u64 t; cvta.to.shared.u64 t, %1; cvt.u32.u64 %0, t; }" : "=r"(a) : "l"(p));
    return a;
}
__device__ __forceinline__ void mma_f16(float* c, const unsigned* a,
                                        unsigned b0, unsigned b1) {
    asm("mma.sync.aligned.m16n8k16.row.col.f32.f16.f16.f32 "
        "{%0,%1,%2,%3},{%4,%5,%6,%7},{%8,%9},{%0,%1,%2,%3};"
        : "+f"(c[0]), "+f"(c[1]), "+f"(c[2]), "+f"(c[3])
        : "r"(a[0]), "r"(a[1]), "r"(a[2]), "r"(a[3]), "r"(b0), "r"(b1));
}
__device__ __forceinline__ void ldmatrix_x4(unsigned* r, uint32_t addr) {
    asm volatile("ldmatrix.sync.aligned.m8n8.x4.shared.b16 {%0,%1,%2,%3}, [%4];"
        : "=r"(r[0]), "=r"(r[1]), "=r"(r[2]), "=r"(r[3]) : "r"(addr));
}
#define CP_ASYNC16(dst, src) \
    asm volatile("cp.async.cg.shared.global [%0], [%1], 16;" :: "r"(dst), "l"(src))
#define CP_ASYNC16_P(dst, src, pred) \
    asm volatile("{ .reg .pred p; setp.ne.u32 p, %2, 0; @p cp.async.cg.shared.global [%0], [%1], 16; }" \
        :: "r"(dst), "l"(src), "r"((unsigned)(pred)))
#define CP_COMMIT() asm volatile("cp.async.commit_group;" ::: "memory")
#define CP_WAIT1()  asm volatile("cp.async.wait_group 1;" ::: "memory")
#define PREFETCH_L2(p) asm volatile("prefetch.global.L2 [%0];" :: "l"(p))
__device__ __forceinline__ uint32_t sw128(uint32_t b) { return b ^ ((b >> 3) & 0x70); }

// ---------------- dtype detect (warp-parallel) ----------------
__device__ __forceinline__ int detect_stride(const int* __restrict__ bk, int n) {
    int lane = threadIdx.x & 31;
    int acc = 0;
    int lim = min(256, n / 2);
    for (int j = lane; j < lim; j += 32) acc |= bk[2 * j + 1];
#pragma unroll
    for (int o = 16; o; o >>= 1) acc |= __shfl_xor_sync(0xffffffffu, acc, o);
    return acc ? 1 : 2;
}

// ---------------- 1: counts + scan (last-CTA ticket) ----------------
__global__ __launch_bounds__(512) void countscan_kernel(const int* __restrict__ bk, int n) {
    __shared__ int sc[NB];
    __shared__ int sstride;
    __shared__ int sticket;
    int tid = threadIdx.x;
    if (tid < 32) {
        int s = detect_stride(bk, n);
        if (tid == 0) sstride = s;
    }
    sc[tid] = 0;
    __syncthreads();
    int stride = sstride;
    for (int i = blockIdx.x * 512 + tid; i < n; i += NCNT_BLK * 512) {
        unsigned b = (unsigned)bk[(size_t)i * stride];
        if (b < NB) atomicAdd(&sc[b], 1);
    }
    __syncthreads();
    g_pcnt[blockIdx.x][tid] = sc[tid];
    __threadfence();
    if (tid == 0) sticket = atomicAdd(&g_tick1, 1);
    __syncthreads();
    if (sticket == NCNT_BLK - 1) {
        int cnt = 0;
        for (int b = 0; b < NCNT_BLK; b++) cnt += g_pcnt[b][tid];
        sc[tid] = cnt;
        __syncthreads();
#pragma unroll
        for (int o = 1; o < NB; o <<= 1) {
            int v = (tid >= o) ? sc[tid - o] : 0;
            __syncthreads();
            sc[tid] += v;
            __syncthreads();
        }
        int excl = sc[tid] - cnt;
        g_off[tid] = excl;
        g_cursor[tid] = excl;
        g_counts[tid] = (float)cnt;
        if (tid == NB - 1) g_off[NB] = sc[tid];
        if (tid == 0) g_tick1 = 0;
    }
}

// ---------------- 2: scatter permutation ----------------
__global__ void scatter_kernel(const int* __restrict__ bk, int n) {
    __shared__ int sstride;
    if (threadIdx.x < 32) {
        int s = detect_stride(bk, n);
        if (threadIdx.x == 0) sstride = s;
    }
    __syncthreads();
    int stride = sstride;
    int i = blockIdx.x * blockDim.x + threadIdx.x;
    if (i < n) {
        unsigned b = (unsigned)bk[(size_t)i * stride];
        if (b < NB) {
            int pos = atomicAdd(&g_cursor[b], 1);
            if ((unsigned)pos < (unsigned)NMAX) g_perm[pos] = i;
        }
    }
}

// ---------------- 3: bucket sums + prototype + P2 row (fused, 2-way) ----------------
__global__ __launch_bounds__(512) void bucketsum_p2_kernel(
    const float* __restrict__ V, const float* __restrict__ Wr, int n) {
    __shared__ float spart[2][ND];
    __shared__ __align__(16) float sp[ND];
    __shared__ int sticket;
    int b = blockIdx.x;
    int tid = threadIdx.x, t = tid & 255, h = tid >> 8;
    int lane = tid & 31, warp = tid >> 5;

    int s0 = g_off[b], s1 = g_off[b + 1];
    int len = s1 - s0;
    int half = (len + 1) >> 1;
    int hs = s0 + h * half;
    int he = min(s1, hs + half);
    float acc = 0.f;
    int i = hs;
    for (; i + 8 <= he; i += 8) {
        int r[8];
#pragma unroll
        for (int j = 0; j < 8; j++) r[j] = __ldcs(&g_perm[i + j]);
#pragma unroll
        for (int j = 0; j < 8; j++) acc += __ldcs(&V[(size_t)r[j] * ND + t]);
    }
    for (; i < he; i++) acc += __ldcs(&V[(size_t)g_perm[i] * ND + t]);
    spart[h][t] = acc;
    __syncthreads();

    float cnt = (float)len;
    if (h == 0) {
        float tot = spart[0][t] + spart[1][t];
        g_sums[(size_t)b * ND + t] = tot;
        sp[t] = (len > 0) ? tot / cnt : 0.f;
    }
    __syncthreads();

    const float4* sp4 = (const float4*)sp;
    if (len > 0) {
        for (int rr = 0; rr < 16; rr++) {
            int r = warp * 16 + rr;
            const float4* w4 = (const float4*)(Wr + (size_t)r * ND);
            float4 p0 = sp4[lane * 2], p1 = sp4[lane * 2 + 1];
            float4 w0 = w4[lane * 2], w1 = w4[lane * 2 + 1];
            float part = p0.x * w0.x + p0.y * w0.y + p0.z * w0.z + p0.w * w0.w +
                         p1.x * w1.x + p1.y * w1.y + p1.z * w1.z + p1.w * w1.w;
#pragma unroll
            for (int o = 16; o; o >>= 1) part += __shfl_xor_sync(0xffffffffu, part, o);
            if (lane == 0) g_P2t[(size_t)r * NB + b] = __float2half(part);
        }
    }
    __threadfence();
    if (tid == 0) sticket = atomicAdd(&g_tick2, 1);
    __syncthreads();
    if (sticket == NB - 1) {
        int any_empty = 0;
        for (int bb = tid; bb < NB; bb += 512) if (g_counts[bb] == 0.f) any_empty = 1;
        __syncthreads();
        spart[0][0] = 0.f;
        __syncthreads();
        if (any_empty) spart[0][0] = 1.f;
        __syncthreads();
        if (spart[0][0] != 0.f) {      // statistically never taken
            if (h == 0) {
                float s = 0.f;
                for (int bb = 0; bb < NB; bb++) s += g_sums[(size_t)bb * ND + t];
                sp[t] = s / (float)n;
            }
            __syncthreads();
            for (int bb = 0; bb < NB; bb++) {
                if (g_counts[bb] != 0.f) continue;
                for (int rr = 0; rr < 16; rr++) {
                    int r = warp * 16 + rr;
                    const float4* w4 = (const float4*)(Wr + (size_t)r * ND);
                    float4 p0 = sp4[lane * 2], p1 = sp4[lane * 2 + 1];
                    float4 w0 = w4[lane * 2], w1 = w4[lane * 2 + 1];
                    float part = p0.x * w0.x + p0.y * w0.y + p0.z * w0.z + p0.w * w0.w +
                                 p1.x * w1.x + p1.y * w1.y + p1.z * w1.z + p1.w * w1.w;
#pragma unroll
                    for (int o = 16; o; o >>= 1) part += __shfl_xor_sync(0xffffffffu, part, o);
                    if (lane == 0) g_P2t[(size_t)r * NB + bb] = __float2half(part);
                }
            }
        }
        if (tid == 0) g_tick2 = 0;
    }
}

// ---------------- per-row softmax core (v in regs -> sE row + coef) ----------------
__device__ __forceinline__ void softmax_row(const float* v, __half* sE, float* sCoef,
                                            float* outc, int r, int row, int lane) {
    float m = v[0];
#pragma unroll
    for (int k = 1; k < 16; k++) m = fmaxf(m, v[k]);
#pragma unroll
    for (int o = 16; o; o >>= 1) m = fmaxf(m, __shfl_xor_sync(0xffffffffu, m, o));
    float Z = 0.f, S = 0.f;
    unsigned h[8];
#pragma unroll
    for (int k = 0; k < 8; k++) {
        float t0 = v[2 * k] - m, t1 = v[2 * k + 1] - m;
        float e0 = __expf(t0), e1 = __expf(t1);
        Z += e0 + e1; S += e0 * t0 + e1 * t1;
        __half2 p = __floats2half2_rn(e0, e1);
        h[k] = *(unsigned*)&p;
    }
#pragma unroll
    for (int o = 16; o; o >>= 1) {
        Z += __shfl_xor_sync(0xffffffffu, Z, o);
        S += __shfl_xor_sync(0xffffffffu, S, o);
    }
    uint4* dst = (uint4*)(sE + r * SE_STRIDE + lane * 16);
    dst[0] = make_uint4(h[0], h[1], h[2], h[3]);
    dst[1] = make_uint4(h[4], h[5], h[6], h[7]);
    float logZ = __logf(Z);
    float entropy = logZ - S / Z;
    float conf = 1.f - entropy * 0.16029938f;     // 1/ln(512)
    if (lane == 0) {
        sCoef[r] = (1.f - conf) / Z;              // gate / Z
        outc[row] = conf;
    }
}

// ---------------- 4: fused main (cp.async-staged Phase A; 1 CTA/SM) ----------------
// Phase A: logits staged via cp.async in 4 chunks of 16 rows x 2KB (sw128-
// swizzled 16B granules), double-buffered; softmax computed from smem.
// Phase B: 16 K-chunks of 32, warp-private cp.async B pipeline (R12 design).
// Phase C: gate+add h_fused (L2-prefetched), LayerNorm, streaming stores.
__global__ __launch_bounds__(256, 1) void main_kernel(
    const float* __restrict__ logits, const float* __restrict__ hfused,
    const float* __restrict__ gamma, const float* __restrict__ beta,
    float* __restrict__ outh, float* __restrict__ outc, int n) {
    extern __shared__ __align__(16) char smem[];
    __half* sE = (__half*)(smem + SE_OFF);
    float* sCoef = (float*)(smem + XCOEF_OFF);
    uint32_t sbase = smem_u32(smem);

    int row0 = blockIdx.x * 64;
    int tid = threadIdx.x, lane = tid & 31, warp = tid >> 5;
    int g = lane >> 2, tg = lane & 3;
    int colbase = warp * 32;

    const char* P2c = (const char*)g_P2t;
    uint32_t sbW = sbase + SB_OFF + warp * SB_WARP;
    int stg_nr = lane >> 2, stg_seg = lane & 3;
#define STAGE_CHUNK(kc, buf)                                                     \
    do {                                                                         \
        _Pragma("unroll")                                                        \
        for (int j = 0; j < 4; j++) {                                            \
            int nr = stg_nr + j * 8;                                             \
            uint32_t dst = sbW + (buf) * SB_BUF + nr * 80 + stg_seg * 16;        \
            const char* src = P2c +                                              \
                ((size_t)(colbase + nr) * NB + (kc) * 32 + stg_seg * 8) * 2;     \
            CP_ASYNC16(dst, src);                                                \
        }                                                                        \
        CP_COMMIT();                                                             \
    } while (0)

    // logits chunk c: rows [row0+16c, row0+16c+16), 32KB, 8 x 16B per thread.
    const char* lgbase = (const char*)(logits + (size_t)row0 * NB);
    long long lgmax = ((long long)n - row0) * NB * 4;   // bytes valid in this tile
#define STAGE_LOGITS(c, buf)                                                     \
    do {                                                                         \
        long long cbase = (long long)(c) * STG_BUF;                              \
        _Pragma("unroll")                                                        \
        for (int j = 0; j < 8; j++) {                                            \
            uint32_t o = (uint32_t)(tid * 16 + j * 4096);                        \
            uint32_t dst = sbase + STG_OFF + (buf) * STG_BUF + sw128(o);         \
            CP_ASYNC16_P(dst, lgbase + cbase + o, (cbase + o) < lgmax);          \
        }                                                                        \
        CP_COMMIT();                                                             \
    } while (0)

    STAGE_CHUNK(0, 0);
    STAGE_CHUNK(1, 1);
    STAGE_LOGITS(0, 0);
    STAGE_LOGITS(1, 1);

    // L2 prefetch of this CTA's hfused tile (64 rows x 1KB = 512 lines; 2/thread).
    {
        const char* hbase = (const char*)(hfused + (size_t)row0 * ND);
        long long maxoff = ((long long)n - row0) * ND * 4;
#pragma unroll
        for (int j = 0; j < 2; j++) {
            long long off = (long long)(tid + j * 256) * 128;
            if (off < maxoff) PREFETCH_L2(hbase + off);
        }
    }

    // ---- Phase A: softmax from staged chunks (warp: 2 rows per chunk)
    const float* stg = (const float*)(smem + STG_OFF);
#pragma unroll 1
    for (int c = 0; c < 4; c++) {
        CP_WAIT1();
        __syncthreads();          // chunk c fully resident for all warps
        int buf = c & 1;
#pragma unroll
        for (int rloc = 0; rloc < 2; rloc++) {
            int rr = warp * 2 + rloc;          // row within chunk
            int r = c * 16 + rr;               // row within tile
            int row = row0 + r;
            if (row < n) {
                float v[16];
#pragma unroll
                for (int q = 0; q < 4; q++) {
                    uint32_t o = (uint32_t)(rr * 2048 + lane * 64 + q * 16);
                    const float4 f = *(const float4*)((const char*)stg +
                                                      buf * STG_BUF + sw128(o));
                    v[4 * q] = f.x; v[4 * q + 1] = f.y;
                    v[4 * q + 2] = f.z; v[4 * q + 3] = f.w;
                }
                softmax_row(v, sE, sCoef, outc, r, row, lane);
            } else {
                uint4* dst = (uint4*)(sE + r * SE_STRIDE + lane * 16);
                dst[0] = make_uint4(0, 0, 0, 0);
                dst[1] = make_uint4(0, 0, 0, 0);
                if (lane == 0) sCoef[r] = 0.f;
            }
        }
        __syncthreads();          // all warps done reading buf before refill
        if (c + 2 < 4) STAGE_LOGITS(c + 2, buf);
        else CP_COMMIT();         // keep group accounting uniform
    }
    __syncthreads();   // sE complete (A fragments cross warps)

    // ---- Phase B: acc = ehat @ P2, 16 K-chunks of 32, warp-private pipeline
    float acc[4][4][4];
#pragma unroll
    for (int mt = 0; mt < 4; mt++)
#pragma unroll
        for (int nt = 0; nt < 4; nt++)
#pragma unroll
            for (int q = 0; q < 4; q++) acc[mt][nt][q] = 0.f;

    int t4 = lane >> 3, r8 = lane & 7;
    uint32_t aBase = sbase + SE_OFF +
        (((uint32_t)((t4 & 1) * 8 + r8)) * SE_STRIDE + (uint32_t)(t4 >> 1) * 8) * 2;
    uint32_t bTileOff = ((uint32_t)((t4 >> 1) * 8 + r8)) * 80u + (uint32_t)(t4 & 1) * 16u;

    for (int kc = 0; kc < 16; kc++) {
        int buf = kc & 1;
        CP_WAIT1();
        uint32_t bBuf = sbW + buf * SB_BUF + bTileOff;
#pragma unroll
        for (int ks = 0; ks < 2; ks++) {
            unsigned a[4][4];
#pragma unroll
            for (int mt = 0; mt < 4; mt++)
                ldmatrix_x4(a[mt], aBase + (uint32_t)(mt * 16 * SE_STRIDE + kc * 32 + ks * 16) * 2);
            unsigned bb[8];
            ldmatrix_x4(bb,     bBuf + ks * 32);              // nt 0,1
            ldmatrix_x4(bb + 4, bBuf + 16 * 80 + ks * 32);    // nt 2,3
#pragma unroll
            for (int nt = 0; nt < 4; nt++)
#pragma unroll
                for (int mt = 0; mt < 4; mt++)
                    mma_f16(acc[mt][nt], a[mt], bb[2 * nt], bb[2 * nt + 1]);
        }
        if (kc + 2 < 16) STAGE_CHUNK(kc + 2, buf);
        else CP_COMMIT();
    }
    __syncthreads();

    // ---- Phase C: fragments -> smem fp32 [64][SH_STRIDE]
    float* sH = (float*)smem;
#pragma unroll
    for (int mt = 0; mt < 4; mt++) {
        int rb = mt * 16;
#pragma unroll
        for (int nt = 0; nt < 4; nt++) {
            int cb = colbase + nt * 8 + 2 * tg;
            sH[(rb + g) * SH_STRIDE + cb]         = acc[mt][nt][0];
            sH[(rb + g) * SH_STRIDE + cb + 1]     = acc[mt][nt][1];
            sH[(rb + g + 8) * SH_STRIDE + cb]     = acc[mt][nt][2];
            sH[(rb + g + 8) * SH_STRIDE + cb + 1] = acc[mt][nt][3];
        }
    }
    __syncthreads();

    // ---- LayerNorm per row (each warp: 8 rows); streaming stores
    float gam[8], bet[8];
#pragma unroll
    for (int k = 0; k < 8; k++) { gam[k] = gamma[lane + 32 * k]; bet[k] = beta[lane + 32 * k]; }
#pragma unroll
    for (int rr = 0; rr < 8; rr++) {
        int r = warp * 8 + rr;
        int row = row0 + r;
        if (row < n) {
            float coef = sCoef[r];
            const float* hrow = hfused + (size_t)row * ND;
            float x[8];
            float s = 0.f, s2 = 0.f;
#pragma unroll
            for (int k = 0; k < 8; k++) {
                int c = lane + 32 * k;
                x[k] = hrow[c] + coef * sH[r * SH_STRIDE + c];
                s += x[k]; s2 += x[k] * x[k];
            }
#pragma unroll
            for (int o = 16; o; o >>= 1) {
                s += __shfl_xor_sync(0xffffffffu, s, o);
                s2 += __shfl_xor_sync(0xffffffffu, s2, o);
            }
            float mean = s * (1.f / ND);
            float var = s2 * (1.f / ND) - mean * mean;
            float rstd = rsqrtf(var + 1e-5f);
            float* orow = outh + (size_t)row * ND;
#pragma unroll
            for (int k = 0; k < 8; k++) {
                int c = lane + 32 * k;
                __stcs(&orow[c], (x[k] - mean) * rstd * gam[k] + bet[k]);
            }
        }
    }
}

// ---------------- launch ----------------
extern "C" void kernel_launch(void* const* d_in, const int* in_sizes, int n_in,
                              void* d_out, int out_size) {
    const float* h_fused = (const float*)d_in[0];
    const float* V       = (const float*)d_in[1];
    const float* logits  = (const float*)d_in[2];
    const int*   bk32    = (const int*)d_in[3];
    const float* Wr      = (const float*)d_in[4];
    const float* gamma   = (const float*)d_in[5];
    const float* beta    = (const float*)d_in[6];
    int n = in_sizes[0] / ND;

    float* outh = (float*)d_out;
    float* outc = outh + (size_t)n * ND;

    cudaFuncSetAttribute(main_kernel, cudaFuncAttributeMaxDynamicSharedMemorySize,
                         SMEM_TOTAL);

    countscan_kernel<<<NCNT_BLK, 512>>>(bk32, n);                    // 1
    scatter_kernel<<<(n + 511) / 512, 512>>>(bk32, n);               // 2
    bucketsum_p2_kernel<<<NB, 512>>>(V, Wr, n);                      // 3
    main_kernel<<<(n + 63) / 64, 256, SMEM_TOTAL>>>(logits, h_fused, gamma, beta,
                                                    outh, outc, n);  // 4 (ncu window)
}